// round 16
// baseline (speedup 1.0000x reference)
#include <cuda_runtime.h>
#include <math.h>

#define IN_DIM 8
#define HID 50
#define BATCH 4096
#define TLEN 512
#define NB 32              // batches per CTA (4 per warp)
#define NT 256
#define GRIDN (BATCH / NB)
#define WKF 256            // Wp floats per k (wrz 128 + wn 64 + pad)
#define HSW 512            // hs floats per warp: 128 16B-slots (bijective P image)
#define KCH 12             // h-part k=0..11 weights cached in regs

typedef unsigned long long ull;

// slot permutation: P(s) = s ^ ((s>>3)&7)  — linear bijection on [0,128)
// float offset of (row r, half h): 4 * P(2r + h)
#define HOF(r, h) (4 * (((2 * (r) + (h)) ^ (((2 * (r) + (h)) >> 3) & 7))))

__device__ __forceinline__ ull mk2(float lo, float hi) {
    ull r; asm("mov.b64 %0, {%1, %2};" : "=l"(r) : "f"(lo), "f"(hi)); return r;
}
__device__ __forceinline__ ull ff2(ull a, ull b, ull c) {
    ull d; asm("fma.rn.f32x2 %0, %1, %2, %3;" : "=l"(d) : "l"(a), "l"(b), "l"(c));
    return d;
}
__device__ __forceinline__ ull add2(ull a, ull b) {
    ull d; asm("add.rn.f32x2 %0, %1, %2;" : "=l"(d) : "l"(a), "l"(b));
    return d;
}
__device__ __forceinline__ float2 up2(ull v) {
    float2 r; asm("mov.b64 {%0, %1}, %2;" : "=f"(r.x), "=f"(r.y) : "l"(v)); return r;
}
__device__ __forceinline__ float tanhapx(float v) {
    float r; asm("tanh.approx.f32 %0, %1;" : "=f"(r) : "f"(v)); return r;
}
__device__ __forceinline__ float fsig(float v) {
    return fmaf(0.5f, tanhapx(0.5f * v), 0.5f);
}

__global__ __launch_bounds__(NT, 1) void gru_kernel(
    const float* __restrict__ x, const float* __restrict__ W_ih,
    const float* __restrict__ W_hh, const float* __restrict__ b_ih,
    const float* __restrict__ b_hh, const float* __restrict__ W_out,
    const float* __restrict__ b_out, float* __restrict__ out)
{
    extern __shared__ float sm[];
    float* Wp = sm;                  // [HID][WKF]  W_hh swizzled (shared)
    float* hs = Wp + HID * WKF;      // [8 warps][HSW]  dup h + dup x, slot-permuted

    const int tid  = threadIdx.x;
    const int lane = tid & 31;
    const int wid  = tid >> 5;
    const int b0w  = blockIdx.x * NB + wid * 4;
    const int c    = lane * 2;                    // c-pair tile (live < 25)
    const bool live = (c < HID);
    float* hw = hs + wid * HSW;

    // per-lane swizzled weight offsets (floats)
    const int wrzOff = (lane & 7) * 4 + (lane >> 3) * 32;          // [0,128)
    const int wnOff  = 128 + (lane & 15) * 2 + (lane >> 4) * 32;   // [128,192)

    // ---- one-time: pack W_hh into swizzled Wp ----
    for (int i = tid; i < HID * WKF; i += NT) {
        int k = i >> 8;
        int r = i & 255;
        float v = 0.0f;
        if (r < 128) {                 // wrz: tile t at (t&7)*4+(t>>3)*32
            int grp = r >> 5, rem = r & 31;
            int t = grp * 8 + (rem >> 2);
            int q = rem & 3;
            int cc = t * 2 + (q & 1);
            int g = q >> 1;
            if (cc < HID) v = W_hh[(g * HID + cc) * HID + k];
        } else if (r < 192) {          // wn: tile t at 128+(t&15)*2+(t>>4)*32
            int rr = r - 128;
            int grp = rr >> 5, rem = rr & 31;
            int t = grp * 16 + (rem >> 1);
            int cc = t * 2 + (rem & 1);
            if (cc < HID) v = W_hh[(2 * HID + cc) * HID + k];
        }
        Wp[i] = v;
    }

    // ---- warp-private init: zero hw; x(0) dup into x rows ----
    for (int i = lane; i < HSW; i += 32) hw[i] = 0.0f;
    // lane -> (j = lane>>2 input dim, b = lane&3 batch)
    const float* xg = x + (size_t)(b0w + (lane & 3)) * TLEN * IN_DIM + (lane >> 2);
    // x slot: row 50+j, half = b>>1, elem pair at +(b&1)*2
    const int xoff = HOF(HID + (lane >> 2), (lane & 3) >> 1) + ((lane & 3) & 1) * 2;
    float xv0 = xg[0];
    *(ull*)&hw[xoff] = mk2(xv0, xv0);
    float xv = xg[IN_DIM];
    __syncthreads();   // Wp visible to all warps

    // ---- per-lane constants in registers ----
    ull bsi[3], bbh[3];
    ull cwx_r[IN_DIM], cwx_z[IN_DIM], cwx_n[IN_DIM];
    #pragma unroll
    for (int g = 0; g < 3; g++) {
        bsi[g] = live ? mk2(b_ih[g * HID + c], b_ih[g * HID + c + 1]) : 0ULL;
        bbh[g] = live ? mk2(b_hh[g * HID + c], b_hh[g * HID + c + 1]) : 0ULL;
    }
    #pragma unroll
    for (int j = 0; j < IN_DIM; j++) {
        if (live) {
            cwx_r[j] = mk2(W_ih[c * IN_DIM + j],             W_ih[(c + 1) * IN_DIM + j]);
            cwx_z[j] = mk2(W_ih[(HID + c) * IN_DIM + j],     W_ih[(HID + c + 1) * IN_DIM + j]);
            cwx_n[j] = mk2(W_ih[(2 * HID + c) * IN_DIM + j], W_ih[(2 * HID + c + 1) * IN_DIM + j]);
        } else { cwx_r[j] = 0ULL; cwx_z[j] = 0ULL; cwx_n[j] = 0ULL; }
    }
    ulonglong2 cwh_rz[KCH]; ull cwh_n[KCH];
    #pragma unroll
    for (int j = 0; j < KCH; j++) {
        cwh_rz[j] = *(const ulonglong2*)&Wp[j * WKF + wrzOff];
        cwh_n[j]  = *(const ull*)&Wp[j * WKF + wnOff];
    }

    // old h for this lane's c-pair, kept in registers (h(0) = 0)
    float hn0[4] = {0.f, 0.f, 0.f, 0.f};
    float hn1[4] = {0.f, 0.f, 0.f, 0.f};

    for (int t = 0; t < TLEN; t++) {
        ull acc[3][4];
        #pragma unroll
        for (int g = 0; g < 3; g++)
            #pragma unroll
            for (int v = 0; v < 4; v++) acc[g][v] = bsi[g];

        // ---- x-part: k = 50..57 (dup x in smem; W in regs) ----
        #pragma unroll
        for (int j = 0; j < IN_DIM; j++) {
            ulonglong2 q0 = *(const ulonglong2*)&hw[HOF(HID + j, 0)];
            ulonglong2 q1 = *(const ulonglong2*)&hw[HOF(HID + j, 1)];
            ull hp[4] = {q0.x, q0.y, q1.x, q1.y};
            #pragma unroll
            for (int v = 0; v < 4; v++) {
                acc[0][v] = ff2(hp[v], cwx_r[j], acc[0][v]);
                acc[1][v] = ff2(hp[v], cwx_z[j], acc[1][v]);
                acc[2][v] = ff2(hp[v], cwx_n[j], acc[2][v]);
            }
        }
        // snapshot gi_n; add b_hh
        ull gis[4];
        #pragma unroll
        for (int v = 0; v < 4; v++) gis[v] = acc[2][v];
        #pragma unroll
        for (int g = 0; g < 3; g++)
            #pragma unroll
            for (int v = 0; v < 4; v++) acc[g][v] = add2(acc[g][v], bbh[g]);

        // ---- h-part k=0..KCH-1 (W in regs) ----
        #pragma unroll
        for (int j = 0; j < KCH; j++) {
            ulonglong2 q0 = *(const ulonglong2*)&hw[HOF(j, 0)];
            ulonglong2 q1 = *(const ulonglong2*)&hw[HOF(j, 1)];
            ull hp[4] = {q0.x, q0.y, q1.x, q1.y};
            #pragma unroll
            for (int v = 0; v < 4; v++) {
                acc[0][v] = ff2(hp[v], cwh_rz[j].x, acc[0][v]);
                acc[1][v] = ff2(hp[v], cwh_rz[j].y, acc[1][v]);
                acc[2][v] = ff2(hp[v], cwh_n[j],    acc[2][v]);
            }
        }
        // ---- h-part k=KCH..49 (W from swizzled smem) ----
        #pragma unroll
        for (int k = KCH; k < HID; k++) {
            ulonglong2 wrz = *(const ulonglong2*)&Wp[k * WKF + wrzOff];
            ull wn = *(const ull*)&Wp[k * WKF + wnOff];
            ulonglong2 q0 = *(const ulonglong2*)&hw[HOF(k, 0)];
            ulonglong2 q1 = *(const ulonglong2*)&hw[HOF(k, 1)];
            ull hp[4] = {q0.x, q0.y, q1.x, q1.y};
            #pragma unroll
            for (int v = 0; v < 4; v++) {
                acc[0][v] = ff2(hp[v], wrz.x, acc[0][v]);
                acc[1][v] = ff2(hp[v], wrz.y, acc[1][v]);
                acc[2][v] = ff2(hp[v], wn,    acc[2][v]);
            }
        }

        // ---- gates in-register (old h lives in hn0/hn1 regs) ----
        if (live) {
            #pragma unroll
            for (int v = 0; v < 4; v++) {
                float2 sr = up2(acc[0][v]);
                float2 sz = up2(acc[1][v]);
                float2 sn = up2(acc[2][v]);
                float2 gi = up2(gis[v]);
                float r0 = fsig(sr.x), z0 = fsig(sz.x);
                float n0 = tanhapx(sn.x + (r0 - 1.0f) * (sn.x - gi.x));
                hn0[v] = n0 + z0 * (hn0[v] - n0);
                float r1 = fsig(sr.y), z1 = fsig(sz.y);
                float n1 = tanhapx(sn.y + (r1 - 1.0f) * (sn.y - gi.y));
                hn1[v] = n1 + z1 * (hn1[v] - n1);
            }
        }

        __syncwarp();   // all lanes done READING hw for step t
        if (live) {
            // dup-store new h: 2 rows x 2 halves, 16B each, slot-permuted
            *(float4*)&hw[HOF(c, 0)]     = make_float4(hn0[0], hn0[0], hn0[1], hn0[1]);
            *(float4*)&hw[HOF(c, 1)]     = make_float4(hn0[2], hn0[2], hn0[3], hn0[3]);
            *(float4*)&hw[HOF(c + 1, 0)] = make_float4(hn1[0], hn1[0], hn1[1], hn1[1]);
            *(float4*)&hw[HOF(c + 1, 1)] = make_float4(hn1[2], hn1[2], hn1[3], hn1[3]);
        }
        if (t + 1 < TLEN) *(ull*)&hw[xoff] = mk2(xv, xv);      // publish x(t+1)
        if (t + 2 < TLEN) xv = xg[(size_t)(t + 2) * IN_DIM];   // prefetch x(t+2)
        __syncwarp();   // writes visible before step t+1 reads
    }

    // ---- linear head: lanes 0-3 handle the warp's 4 batches ----
    // final h(T) is in hw (stored at t = TLEN-1); batch b: half = b>>1, elem (b&1)*2
    if (lane < 4) {
        float a = b_out[0];
        #pragma unroll
        for (int cc = 0; cc < HID; cc++)
            a += hw[HOF(cc, lane >> 1) + (lane & 1) * 2] * W_out[cc];
        out[b0w + lane] = a;
    }
}

extern "C" void kernel_launch(void* const* d_in, const int* in_sizes, int n_in,
                              void* d_out, int out_size) {
    const float* x     = (const float*)d_in[0];
    const float* W_ih  = (const float*)d_in[1];
    const float* W_hh  = (const float*)d_in[2];
    const float* b_ih  = (const float*)d_in[3];
    const float* b_hh  = (const float*)d_in[4];
    const float* W_out = (const float*)d_in[5];
    const float* b_out = (const float*)d_in[6];
    float* out = (float*)d_out;

    size_t smem = (size_t)(HID * WKF + 8 * HSW) * sizeof(float);
    cudaFuncSetAttribute(gru_kernel,
                         cudaFuncAttributeMaxDynamicSharedMemorySize, (int)smem);
    gru_kernel<<<GRIDN, NT, smem>>>(x, W_ih, W_hh, b_ih, b_hh, W_out, b_out, out);
}